// round 17
// baseline (speedup 1.0000x reference)
#include <cuda_runtime.h>
#include <cuda_pipeline.h>
#include <stdint.h>

// ROISelect: per-row top-k(score) + ROI gather, monolithic, sort-free.
// One CTA (1024 thr) per row. The scan streams the row through a 4-deep
// cp.async (LDGSTS) smem ring: in-flight data lives in the async queue, not
// registers, breaking the MLP~2 ceiling imposed by the 64-reg cap at
// TPB=1024 (R16 lesson: register-batched loads cannot exceed ~3.4 TB/s).
// Each thread copies and later consumes ITS OWN 16B per chunk, so no block
// syncs inside the pipeline. Filter score >= 2.80 (~335 cand/row, 4.3-sigma
// margin) into smem; exact sorted ranks via split all-pairs comparison
// (2 threads/candidate, unique u64 keys value|~index, tf.nn.top_k tie
// order); out[rank] written directly. Exact 12-bit radix-select fallback if
// count is outside [256, 4096].

#define B_ROWS 128
#define N_COLS 131072
#define K_TOP  256
#define TPB    1024
#define CAP    4096
#define V4_PER_THREAD (N_COLS / 4 / TPB)   // 32 chunks of 16B per thread
#define DEPTH  4                           // cp.async ring depth
#define CHUNK_FLOATS (TPB * 4)             // 4096 floats = 16KB per chunk

// Dynamic smem arena layout (u64-aligned):
//   buf   : DEPTH * CHUNK_FLOATS floats = 64 KB   (cp.async ring)
//   cand  : CAP u64                     = 32 KB   (also fallback hist+sdata)
//   s_half: TPB u32                     =  4 KB
#define ARENA_BYTES (DEPTH * CHUNK_FLOATS * 4 + CAP * 8 + TPB * 4)  // 102400

__device__ __forceinline__ unsigned int f2u(float f) {
    unsigned int b = __float_as_uint(f);
    return (b & 0x80000000u) ? ~b : (b | 0x80000000u);
}
__device__ __forceinline__ float u2f(unsigned int u) {
    unsigned int b = (u & 0x80000000u) ? (u ^ 0x80000000u) : ~u;
    return __uint_as_float(b);
}

__global__ __launch_bounds__(TPB, 1)
void roiselect_kernel(const float* __restrict__ score,
                      const float* __restrict__ roi,
                      float* __restrict__ out_roi,
                      float* __restrict__ out_score)
{
    __shared__ int s_cnt;
    __shared__ int s_bin;
    extern __shared__ unsigned long long arena[];
    float*              buf    = (float*)arena;                    // 64 KB ring
    unsigned long long* cand   = arena + (DEPTH * CHUNK_FLOATS / 2); // 32 KB
    unsigned int*       s_half = (unsigned int*)(cand + CAP);        // 4 KB

    const int tid = threadIdx.x;
    const int row = blockIdx.x;
    const float* base = score + (size_t)row * N_COLS;

    if (tid == 0) s_cnt = 0;
    __syncthreads();

    // ---------- cp.async pipelined streaming filter ----------
    const float TGUESS = 2.80f;
    // Prologue: stage chunks 0..DEPTH-1 (one 16B copy + commit per chunk).
    #pragma unroll
    for (int k = 0; k < DEPTH; ++k) {
        __pipeline_memcpy_async(&buf[k * CHUNK_FLOATS + tid * 4],
                                base + k * CHUNK_FLOATS + tid * 4,
                                16);
        __pipeline_commit();
    }
    for (int i = 0; i < V4_PER_THREAD; ++i) {
        __pipeline_wait_prior(DEPTH - 1);        // chunk i's group complete
        const int slot = i & (DEPTH - 1);
        float4 f = *(const float4*)&buf[slot * CHUNK_FLOATS + tid * 4];
        // Refill this slot with chunk i+DEPTH before processing (overlap).
        if (i + DEPTH < V4_PER_THREAD) {
            __pipeline_memcpy_async(&buf[slot * CHUNK_FLOATS + tid * 4],
                                    base + (i + DEPTH) * CHUNK_FLOATS + tid * 4,
                                    16);
        }
        __pipeline_commit();                     // keep group count uniform

        const int ebase = i * CHUNK_FLOATS + tid * 4;
        float vals[4] = {f.x, f.y, f.z, f.w};
        #pragma unroll
        for (int c = 0; c < 4; ++c) {
            if (vals[c] >= TGUESS) {
                int pos = atomicAdd(&s_cnt, 1);
                if (pos < CAP) {
                    unsigned int uu = __float_as_uint(vals[c]) | 0x80000000u;
                    cand[pos] = ((unsigned long long)uu << 32)
                              | (unsigned int)~(unsigned int)(ebase + c);
                }
            }
        }
    }
    __syncthreads();
    unsigned int count = (unsigned int)s_cnt;

    // ---------- Exact fallback: 12-bit radix select (never taken on this data) ----------
    if (count < K_TOP || count > CAP) {
        const float4* sc4 = (const float4*)base;
        unsigned int* hist  = (unsigned int*)cand;   // 4096 bins (aliased)
        unsigned int* sdata = hist + 4096;           // 1024 thread sums
        for (int i = tid; i < 4096; i += TPB) hist[i] = 0;
        if (tid == 0) s_cnt = 0;
        __syncthreads();

        for (int i = 0; i < V4_PER_THREAD; ++i) {
            float4 f = sc4[tid + i * TPB];
            float vals[4] = {f.x, f.y, f.z, f.w};
            #pragma unroll
            for (int c = 0; c < 4; ++c)
                atomicAdd(&hist[f2u(vals[c]) >> 20], 1u);
        }
        __syncthreads();

        unsigned int h0 = hist[4*tid+0], h1 = hist[4*tid+1];
        unsigned int h2 = hist[4*tid+2], h3 = hist[4*tid+3];
        sdata[tid] = h0 + h1 + h2 + h3;
        __syncthreads();
        for (int d = 1; d < TPB; d <<= 1) {          // inclusive suffix scan
            unsigned int vv = (tid + d < TPB) ? sdata[tid + d] : 0u;
            __syncthreads();
            sdata[tid] += vv;
            __syncthreads();
        }
        unsigned int Anext = (tid + 1 < TPB) ? sdata[tid + 1] : 0u;
        unsigned int cum3 = Anext + h3;
        unsigned int cum2 = cum3 + h2;
        unsigned int cum1 = cum2 + h1;
        unsigned int cum0 = cum1 + h0;
        if (cum3 >= K_TOP && Anext < K_TOP) s_bin = 4*tid + 3;
        if (cum2 >= K_TOP && cum3  < K_TOP) s_bin = 4*tid + 2;
        if (cum1 >= K_TOP && cum2  < K_TOP) s_bin = 4*tid + 1;
        if (cum0 >= K_TOP && cum1  < K_TOP) s_bin = 4*tid + 0;
        __syncthreads();
        unsigned int uthr = (unsigned int)s_bin << 20;
        __syncthreads();   // uthr read by all; hist region can be overwritten

        for (int i = 0; i < V4_PER_THREAD; ++i) {
            int v4i = tid + i * TPB;
            float4 f = sc4[v4i];
            int ebase = v4i * 4;
            float vals[4] = {f.x, f.y, f.z, f.w};
            #pragma unroll
            for (int c = 0; c < 4; ++c) {
                unsigned int u = f2u(vals[c]);
                if (u >= uthr) {
                    int pos = atomicAdd(&s_cnt, 1);
                    if (pos < CAP)
                        cand[pos] = ((unsigned long long)u << 32)
                                  | (unsigned int)~(unsigned int)(ebase + c);
                }
            }
        }
        __syncthreads();
        count = min((unsigned int)s_cnt, (unsigned int)CAP);
    }

    // Pad to even for the ulonglong2 loops (a 0 key never outranks a real
    // key: all real keys have bit 63 set). count==CAP is even, so the pad
    // write never exceeds the buffer.
    if (tid == 0 && (count & 1u)) cand[count] = 0ULL;
    __syncthreads();
    const int pairs = (int)((count + 1u) >> 1);
    const ulonglong2* c2 = (const ulonglong2*)cand;

    if (count <= 512) {
        // ---------- Split rank: 2 threads per candidate ----------
        const int t     = tid & 511;            // candidate id
        const int which = tid >> 9;             // 0 = low half, 1 = high half
        const int ph    = pairs >> 1;
        const int i0    = which ? ph : 0;
        const int i1    = which ? pairs : ph;
        unsigned int partial = 0;
        if (t < (int)count) {
            const unsigned long long key = cand[t];
            #pragma unroll 4
            for (int i = i0; i < i1; ++i) {
                ulonglong2 p = c2[i];
                partial += (p.x > key) + (p.y > key);
            }
        }
        s_half[tid] = partial;
        __syncthreads();

        if (tid < (int)count) {
            unsigned int rank = s_half[tid] + s_half[tid + 512];
            if (rank < K_TOP) {
                unsigned long long key = cand[tid];
                unsigned int u   = (unsigned int)(key >> 32);
                unsigned int idx = ~(unsigned int)key;
                const float4* r4 = (const float4*)roi;
                float4 rv = r4[(size_t)row * N_COLS + idx];
                out_score[row * K_TOP + rank] = u2f(u);
                ((float4*)out_roi)[row * K_TOP + rank] = rv;
            }
        }
    } else {
        // ---------- Serial rank (fallback-sized candidate sets only) ----------
        for (int c = tid; c < (int)count; c += TPB) {
            unsigned long long key = cand[c];
            int rank = 0;
            #pragma unroll 8
            for (int i = 0; i < pairs; ++i) {
                ulonglong2 p = c2[i];
                rank += (p.x > key) + (p.y > key);
            }
            if (rank < K_TOP) {
                unsigned int u   = (unsigned int)(key >> 32);
                unsigned int idx = ~(unsigned int)key;
                const float4* r4 = (const float4*)roi;
                float4 rv = r4[(size_t)row * N_COLS + idx];
                out_score[row * K_TOP + rank] = u2f(u);
                ((float4*)out_roi)[row * K_TOP + rank] = rv;
            }
        }
    }
}

extern "C" void kernel_launch(void* const* d_in, const int* in_sizes, int n_in,
                              void* d_out, int out_size) {
    (void)in_sizes; (void)n_in; (void)out_size;
    const float* score = (const float*)d_in[0];
    const float* roi   = (const float*)d_in[1];
    float* out_roi   = (float*)d_out;                               // [128,256,4]
    float* out_score = (float*)d_out + (size_t)B_ROWS * K_TOP * 4;  // [128,256]

    static int attr_set = 0;
    if (!attr_set) {
        cudaFuncSetAttribute(roiselect_kernel,
                             cudaFuncAttributeMaxDynamicSharedMemorySize,
                             ARENA_BYTES);
        attr_set = 1;
    }
    roiselect_kernel<<<B_ROWS, TPB, ARENA_BYTES>>>(
        score, roi, out_roi, out_score);
}